// round 7
// baseline (speedup 1.0000x reference)
#include <cuda_runtime.h>
#include <math.h>

#define BB 2
#define CC 8
#define MM 8
#define HH 8
#define FF 256
#define WW 512
#define HD 32
#define BMFW (BB*MM*FF*WW)   // 2,097,152
#define NT  (BB*MM*HH)       // 128 attention tiles
#define WW2 (WW*WW)          // 262144

// ---- scratch (static device memory; no allocation) ----
__device__ float g_c1[3*BMFW];     // conv1 outputs for q,k,v
__device__ float g_lin[3*BMFW];    // lin outputs q,k,v
__device__ float g_qkv[3*BMFW];    // q,k,v post conv2(+rotary), layout [b][m][f][w]
__device__ float g_at[BMFW];       // attention out, layout [b][m][w][f]
__device__ float g_p[(size_t)NT*WW2];  // exp(S) (unnormalized), [tile][r][j]
__device__ float g_sinv[NT*WW];    // 1/rowsum
__device__ float g_rotc[16*WW];
__device__ float g_rots[16*WW];

// ============================================================
// Kernel 0: rotary table
// ============================================================
__global__ void rot_table_kernel()
{
    int i = blockIdx.x, w = threadIdx.x;
    float invf = expf(-(float)i * (9.210340371976184f / 16.0f));
    float sn, cs;
    sincosf((float)w * invf, &sn, &cs);
    g_rotc[i*WW + w] = cs;
    g_rots[i*WW + w] = sn;
}

// ============================================================
// Kernel 1: 3x3 conv, 8->8 ch, all three projections at once.
// ============================================================
__global__ __launch_bounds__(256) void conv1_kernel(
    const float* __restrict__ x,
    const float* __restrict__ wq,
    const float* __restrict__ wk,
    const float* __restrict__ wv)
{
    int f = blockIdx.x, b = blockIdx.y;
    extern __shared__ float sm[];
    float* xs = sm;                      // [3][CC][WW+2]
    float* wt = sm + 3*CC*(WW+2);        // [3][MM][CC][9]
    int tid = threadIdx.x;

    for (int idx = tid; idx < 3*CC*(WW+2); idx += 256) {
        int r   = idx / (CC*(WW+2));
        int rem = idx % (CC*(WW+2));
        int c   = rem / (WW+2);
        int w   = rem % (WW+2) - 1;
        int fr  = f + r - 1;
        float v = 0.f;
        if (fr >= 0 && fr < FF && w >= 0 && w < WW)
            v = x[((b*CC + c)*FF + fr)*WW + w];
        xs[idx] = v;
    }
    for (int idx = tid; idx < MM*CC*9; idx += 256) {
        wt[idx]              = wq[idx];
        wt[idx +   MM*CC*9]  = wk[idx];
        wt[idx + 2*MM*CC*9]  = wv[idx];
    }
    __syncthreads();

    for (int o = tid; o < 3*MM*WW; o += 256) {
        int p = o / (MM*WW);
        int m = (o / WW) % MM;
        int w = o % WW;
        const float* wpt = wt + (p*MM + m)*CC*9;
        float acc = 0.f;
        #pragma unroll
        for (int c = 0; c < CC; c++) {
            #pragma unroll
            for (int r = 0; r < 3; r++) {
                const float* xr = xs + (r*CC + c)*(WW+2) + w;
                acc += xr[0]*wpt[c*9 + r*3 + 0];
                acc += xr[1]*wpt[c*9 + r*3 + 1];
                acc += xr[2]*wpt[c*9 + r*3 + 2];
            }
        }
        g_c1[p*BMFW + ((b*MM + m)*FF + f)*WW + w] = acc;
    }
}

// ============================================================
// Kernel 2: batched GEMM, 128x64 tiles, 8x4 microtile.
// ============================================================
__global__ __launch_bounds__(256) void gemm_lin_kernel(
    const float* __restrict__ Aq,
    const float* __restrict__ Ak,
    const float* __restrict__ Av)
{
    __shared__ float As[128*17];
    __shared__ float Bs[16*64];
    int z = blockIdx.z;
    int p = z >> 4;
    int n = z & 15;
    int m = n % MM;
    int g0 = blockIdx.y * 128, w0 = blockIdx.x * 64;
    const float* A = (p == 0) ? Aq : (p == 1) ? Ak : Av;
    const float* Ap = A + m*FF*FF;
    const float* Bp = g_c1  + (size_t)p*BMFW + (size_t)n*FF*WW;
    float*       Cp = g_lin + (size_t)p*BMFW + (size_t)n*FF*WW;
    int tx = threadIdx.x, ty = threadIdx.y;
    int tid = ty*16 + tx;

    float acc[8][4] = {};
    for (int f0 = 0; f0 < FF; f0 += 16) {
        #pragma unroll
        for (int u = 0; u < 2; u++) {
            int idx = tid + u*256;
            int r = idx >> 2;
            int c4 = (idx & 3) * 4;
            float4 a4 = *(const float4*)(Ap + (g0+r)*FF + f0 + c4);
            As[r*17 + c4+0] = a4.x; As[r*17 + c4+1] = a4.y;
            As[r*17 + c4+2] = a4.z; As[r*17 + c4+3] = a4.w;
        }
        {
            int fl = tid >> 4;
            int wl = (tid & 15) * 4;
            *(float4*)(Bs + fl*64 + wl) =
                *(const float4*)(Bp + (f0+fl)*WW + w0 + wl);
        }
        __syncthreads();
        #pragma unroll
        for (int k = 0; k < 16; k++) {
            float a[8];
            #pragma unroll
            for (int i = 0; i < 8; i++) a[i] = As[(ty*8+i)*17 + k];
            float4 b4 = *(const float4*)(Bs + k*64 + tx*4);
            float bf[4] = {b4.x, b4.y, b4.z, b4.w};
            #pragma unroll
            for (int i = 0; i < 8; i++)
                #pragma unroll
                for (int j = 0; j < 4; j++)
                    acc[i][j] += a[i]*bf[j];
        }
        __syncthreads();
    }
    #pragma unroll
    for (int i = 0; i < 8; i++) {
        float4 o4 = make_float4(acc[i][0], acc[i][1], acc[i][2], acc[i][3]);
        *(float4*)(Cp + (g0 + ty*8 + i)*WW + w0 + tx*4) = o4;
    }
}

// ============================================================
// Kernel 3: 1x3 conv across M + rotary, all 3 projections (z).
// ============================================================
__global__ __launch_bounds__(256) void conv2_rot_kernel(
    const float* __restrict__ wq2,
    const float* __restrict__ wk2,
    const float* __restrict__ wv2)
{
    int e = blockIdx.x, b = blockIdx.y, p = blockIdx.z;
    int f0 = 2*e;
    int apply_rot = (p < 2);
    const float* wc2 = (p == 0) ? wq2 : (p == 1) ? wk2 : wv2;
    const float* src = g_lin + (size_t)p*BMFW;
    float*       dst = g_qkv + (size_t)p*BMFW;

    __shared__ float hs[2*MM*(WW+2)];
    __shared__ float wt[MM*MM*3];
    __shared__ float rc[WW], rs[WW];
    int tid = threadIdx.x;

    for (int idx = tid; idx < 2*MM*(WW+2); idx += 256) {
        int rr  = idx / (MM*(WW+2));
        int rem = idx % (MM*(WW+2));
        int mm  = rem / (WW+2);
        int w   = rem % (WW+2) - 1;
        float v = 0.f;
        if (w >= 0 && w < WW)
            v = src[((b*MM + mm)*FF + f0 + rr)*WW + w];
        hs[idx] = v;
    }
    for (int idx = tid; idx < MM*MM*3; idx += 256) wt[idx] = wc2[idx];
    if (apply_rot) {
        int i = e % (HD/2);
        for (int w = tid; w < WW; w += 256) {
            rc[w] = g_rotc[i*WW + w];
            rs[w] = g_rots[i*WW + w];
        }
    }
    __syncthreads();

    for (int o = tid; o < MM*WW; o += 256) {
        int m = o / WW, w = o % WW;
        float c0 = 0.f, c1 = 0.f;
        #pragma unroll
        for (int mm = 0; mm < MM; mm++) {
            float k0 = wt[(m*MM+mm)*3+0];
            float k1 = wt[(m*MM+mm)*3+1];
            float k2 = wt[(m*MM+mm)*3+2];
            const float* h0 = hs + mm*(WW+2) + w;
            const float* h1 = hs + (MM+mm)*(WW+2) + w;
            c0 += h0[0]*k0 + h0[1]*k1 + h0[2]*k2;
            c1 += h1[0]*k0 + h1[1]*k1 + h1[2]*k2;
        }
        float o0 = c0, o1 = c1;
        if (apply_rot) {
            float cs = rc[w], sn = rs[w];
            o0 = c0*cs - c1*sn;
            o1 = c1*cs + c0*sn;
        }
        dst[((b*MM + m)*FF + f0    )*WW + w] = o0;
        dst[((b*MM + m)*FF + f0 + 1)*WW + w] = o1;
    }
}

// ============================================================
// Kernel 4a: S = QK^T/16 + prev  -> qk_out;  P = exp(S) -> g_p;
// row sums -> g_sinv.  No max subtraction (|S| < ~0.7, safe).
// Grid (4 rowblocks, 128 tiles), 256 threads, 128x128 chunks,
// 8x8 microtile, K=32.
// ============================================================
#define QPAD 132

__global__ __launch_bounds__(256) void attn_s_kernel(
    const float* __restrict__ prev_qk,
    float* __restrict__ qk_out)
{
    int rb = blockIdx.x, t = blockIdx.y;
    int r0 = rb * 128;
    int h = t % HH, m = (t / HH) % MM, b = t / (HH*MM);

    __shared__ float Qt[32*QPAD];       // [k][r] 16.9 KB
    __shared__ float Kt[32*QPAD];       // [k][j]
    __shared__ float part[16*128];      // rowsum partials

    int tid = threadIdx.x;
    int tx = tid & 15, ty = tid >> 4;

    const float* Qb = g_qkv + 0*BMFW + ((b*MM+m)*FF + h*HD)*WW;
    const float* Kb = g_qkv + 1*BMFW + ((b*MM+m)*FF + h*HD)*WW;
    const float* Pq   = prev_qk + (size_t)t*WW2;
    float*       Sout = qk_out  + (size_t)t*WW2;
    float*       Pout = g_p     + (size_t)t*WW2;

    // load Q^T subtile: Qt[k][r], r in [r0, r0+128)
    #pragma unroll
    for (int u = 0; u < 4; u++) {
        int fid = tid + u*256;          // [0,1024)
        int d   = fid >> 5;             // 32 k-rows
        int c4  = (fid & 31) * 4;       // 128 floats/row
        float4 q4 = *(const float4*)(Qb + d*WW + r0 + c4);
        *(float4*)(Qt + d*QPAD + c4) = q4;
    }

    float rsum[8];
    #pragma unroll
    for (int i = 0; i < 8; i++) rsum[i] = 0.f;

    const float scale = 0.0625f;

    for (int cc = 0; cc < 4; cc++) {
        int j0 = cc * 128;
        __syncthreads();
        #pragma unroll
        for (int u = 0; u < 4; u++) {
            int fid = tid + u*256;
            int d   = fid >> 5;
            int c4  = (fid & 31) * 4;
            float4 k4 = *(const float4*)(Kb + d*WW + j0 + c4);
            *(float4*)(Kt + d*QPAD + c4) = k4;
        }
        __syncthreads();

        float acc[8][8];
        #pragma unroll
        for (int i = 0; i < 8; i++)
            #pragma unroll
            for (int j = 0; j < 8; j++) acc[i][j] = 0.f;

        #pragma unroll 4
        for (int k = 0; k < 32; k++) {
            float4 a0 = *(const float4*)(Qt + k*QPAD + ty*8);
            float4 a1 = *(const float4*)(Qt + k*QPAD + ty*8 + 4);
            float4 b0 = *(const float4*)(Kt + k*QPAD + tx*8);
            float4 b1 = *(const float4*)(Kt + k*QPAD + tx*8 + 4);
            float av[8] = {a0.x,a0.y,a0.z,a0.w,a1.x,a1.y,a1.z,a1.w};
            float bv[8] = {b0.x,b0.y,b0.z,b0.w,b1.x,b1.y,b1.z,b1.w};
            #pragma unroll
            for (int i = 0; i < 8; i++)
                #pragma unroll
                for (int j = 0; j < 8; j++)
                    acc[i][j] += av[i]*bv[j];
        }

        // epilogue: add prev, write S, exp, write P, rowsum
        #pragma unroll
        for (int i = 0; i < 8; i++) {
            size_t rowoff = (size_t)(r0 + ty*8 + i)*WW + j0 + tx*8;
            #pragma unroll
            for (int v = 0; v < 2; v++) {
                float4 pq4 = *(const float4*)(Pq + rowoff + v*4);
                float4 s4;
                s4.x = fmaf(acc[i][v*4+0], scale, pq4.x);
                s4.y = fmaf(acc[i][v*4+1], scale, pq4.y);
                s4.z = fmaf(acc[i][v*4+2], scale, pq4.z);
                s4.w = fmaf(acc[i][v*4+3], scale, pq4.w);
                *(float4*)(Sout + rowoff + v*4) = s4;
                float4 e4;
                e4.x = __expf(s4.x); e4.y = __expf(s4.y);
                e4.z = __expf(s4.z); e4.w = __expf(s4.w);
                *(float4*)(Pout + rowoff + v*4) = e4;
                rsum[i] += e4.x + e4.y + e4.z + e4.w;
            }
        }
    }

    // reduce rowsums across tx
    #pragma unroll
    for (int i = 0; i < 8; i++) part[tx*128 + ty*8 + i] = rsum[i];
    __syncthreads();
    if (tid < 128) {
        float s = 0.f;
        #pragma unroll
        for (int u = 0; u < 16; u++) s += part[u*128 + tid];
        g_sinv[t*WW + r0 + tid] = 1.0f / s;
    }
}

// ============================================================
// Kernel 4b: A = P V, normalized by sinv.  C[r][d] = sum_j P[r][j] V[d][j].
// Grid (4 rowblocks, 128 tiles), 256 threads, output 128x32.
// ============================================================
__global__ __launch_bounds__(256) void attn_pv_kernel()
{
    int rb = blockIdx.x, t = blockIdx.y;
    int r0 = rb * 128;
    int h = t % HH, m = (t / HH) % MM, b = t / (HH*MM);

    __shared__ float Ps[128*36];   // [r][k] 18.4 KB
    __shared__ float Vs[32*36];    // [d][k]

    int tid = threadIdx.x;
    int tx = tid & 7, ty = tid >> 3;   // tx: 8 d-groups, ty: 32 r-groups

    const float* Vb = g_qkv + 2*BMFW + ((b*MM+m)*FF + h*HD)*WW;
    const float* Pp = g_p + (size_t)t*WW2;
    float*       At = g_at + (size_t)(b*MM+m)*WW*FF + h*HD;

    float acc[4][4] = {};

    for (int kc = 0; kc < 16; kc++) {
        int k0 = kc * 32;
        __syncthreads();
        #pragma unroll
        for (int u = 0; u < 4; u++) {
            int fid = tid + u*256;      // [0,1024)
            int row = fid >> 3;
            int c4  = (fid & 7) * 4;
            float4 p4 = *(const float4*)(Pp + (size_t)(r0+row)*WW + k0 + c4);
            *(float4*)(Ps + row*36 + c4) = p4;
        }
        {
            int d  = tid >> 3;
            int c4 = (tid & 7) * 4;
            float4 v4 = *(const float4*)(Vb + d*WW + k0 + c4);
            *(float4*)(Vs + d*36 + c4) = v4;
        }
        __syncthreads();

        #pragma unroll
        for (int k4 = 0; k4 < 32; k4 += 4) {
            float4 a[4], bv[4];
            #pragma unroll
            for (int i = 0; i < 4; i++)
                a[i] = *(const float4*)(Ps + (ty*4+i)*36 + k4);
            #pragma unroll
            for (int j = 0; j < 4; j++)
                bv[j] = *(const float4*)(Vs + (tx*4+j)*36 + k4);
            #pragma unroll
            for (int i = 0; i < 4; i++)
                #pragma unroll
                for (int j = 0; j < 4; j++)
                    acc[i][j] += a[i].x*bv[j].x + a[i].y*bv[j].y
                               + a[i].z*bv[j].z + a[i].w*bv[j].w;
        }
    }

    #pragma unroll
    for (int i = 0; i < 4; i++) {
        int r = r0 + ty*4 + i;
        float is = g_sinv[t*WW + r];
        float4 o4 = make_float4(acc[i][0]*is, acc[i][1]*is,
                                acc[i][2]*is, acc[i][3]*is);
        *(float4*)(At + (size_t)r*FF + tx*4) = o4;
    }
}

// ============================================================
// Kernel 5: out projection, 128x64 tiles, 8x4 microtile.
// ============================================================
__global__ __launch_bounds__(256) void gemm_out_kernel(
    const float* __restrict__ A,
    const float* __restrict__ Bt,
    float* __restrict__ Cx)
{
    __shared__ float As[128*17];
    __shared__ float Bs[64*17];
    int n = blockIdx.z;
    int m = n % MM;
    int g0 = blockIdx.y * 128, w0 = blockIdx.x * 64;
    const float* Ap = A  + m*FF*FF;
    const float* Bp = Bt + (size_t)n*WW*FF;
    int tx = threadIdx.x, ty = threadIdx.y;
    int tid = ty*16 + tx;

    float acc[8][4] = {};
    for (int f0 = 0; f0 < FF; f0 += 16) {
        #pragma unroll
        for (int u = 0; u < 2; u++) {
            int idx = tid + u*256;
            int r = idx >> 2;
            int c4 = (idx & 3) * 4;
            float4 a4 = *(const float4*)(Ap + (g0+r)*FF + f0 + c4);
            As[r*17 + c4+0] = a4.x; As[r*17 + c4+1] = a4.y;
            As[r*17 + c4+2] = a4.z; As[r*17 + c4+3] = a4.w;
        }
        {
            int wl = tid >> 2;
            int c4 = (tid & 3) * 4;
            float4 b4 = *(const float4*)(Bp + (size_t)(w0+wl)*FF + f0 + c4);
            Bs[wl*17 + c4+0] = b4.x; Bs[wl*17 + c4+1] = b4.y;
            Bs[wl*17 + c4+2] = b4.z; Bs[wl*17 + c4+3] = b4.w;
        }
        __syncthreads();
        #pragma unroll
        for (int k = 0; k < 16; k++) {
            float a[8], bf[4];
            #pragma unroll
            for (int i = 0; i < 8; i++) a[i]  = As[(ty*8+i)*17 + k];
            #pragma unroll
            for (int j = 0; j < 4; j++) bf[j] = Bs[(tx*4+j)*17 + k];
            #pragma unroll
            for (int i = 0; i < 8; i++)
                #pragma unroll
                for (int j = 0; j < 4; j++)
                    acc[i][j] += a[i]*bf[j];
        }
        __syncthreads();
    }
    #pragma unroll
    for (int i = 0; i < 8; i++) {
        float4 o4 = make_float4(acc[i][0], acc[i][1], acc[i][2], acc[i][3]);
        *(float4*)(Cx + ((size_t)n*FF + g0 + ty*8 + i)*WW + w0 + tx*4) = o4;
    }
}

// ============================================================
extern "C" void kernel_launch(void* const* d_in, const int* in_sizes, int n_in,
                              void* d_out, int out_size)
{
    const float* x       = (const float*)d_in[0];
    const float* prev_qk = (const float*)d_in[1];
    const float* ow      = (const float*)d_in[11];

    float* out_ptr = (float*)d_out;                // (B,M,F,W) first
    float* qk_ptr  = out_ptr + (size_t)BMFW;       // (B,M,H,W,W) second

    float* p_at;
    cudaGetSymbolAddress((void**)&p_at, g_at);

    // rotary table
    rot_table_kernel<<<16, WW>>>();

    // conv1
    int conv1_smem = (3*CC*(WW+2) + 3*MM*CC*9) * 4;
    cudaFuncSetAttribute(conv1_kernel,
        cudaFuncAttributeMaxDynamicSharedMemorySize, conv1_smem);
    conv1_kernel<<<dim3(FF, BB), 256, conv1_smem>>>(
        x, (const float*)d_in[2], (const float*)d_in[5], (const float*)d_in[8]);

    // lin GEMMs
    gemm_lin_kernel<<<dim3(WW/64, FF/128, 3*BB*MM), dim3(16,16)>>>(
        (const float*)d_in[3], (const float*)d_in[6], (const float*)d_in[9]);

    // conv2 (+rotary)
    conv2_rot_kernel<<<dim3(FF/2, BB, 3), 256>>>(
        (const float*)d_in[4], (const float*)d_in[7], (const float*)d_in[10]);

    // attention: S+softmax GEMM, then PV GEMM
    attn_s_kernel<<<dim3(4, NT), 256>>>(prev_qk, qk_ptr);
    attn_pv_kernel<<<dim3(4, NT), 256>>>();

    // output projection
    gemm_out_kernel<<<dim3(WW/64, FF/128, BB*MM), dim3(16,16)>>>(ow, p_at, out_ptr);
}

// round 10
// speedup vs baseline: 1.1995x; 1.1995x over previous
#include <cuda_runtime.h>
#include <math.h>

#define BB 2
#define CC 8
#define MM 8
#define HH 8
#define FF 256
#define WW 512
#define HD 32
#define BMFW (BB*MM*FF*WW)   // 2,097,152
#define NT  (BB*MM*HH)       // 128 attention tiles
#define WW2 (WW*WW)          // 262144

// ---- scratch (static device memory; no allocation) ----
__device__ float g_c1[3*BMFW];     // conv1 outputs for q,k,v
__device__ float g_lin[3*BMFW];    // lin outputs q,k,v
__device__ float g_qkv[3*BMFW];    // q,k,v post conv2(+rotary), layout [b][m][f][w]
__device__ float g_at[BMFW];       // attention out, layout [b][m][w][f]
__device__ float g_rotc[16*WW];
__device__ float g_rots[16*WW];

// ============================================================
// Kernel 0: rotary table
// ============================================================
__global__ void rot_table_kernel()
{
    int i = blockIdx.x, w = threadIdx.x;
    float invf = expf(-(float)i * (9.210340371976184f / 16.0f));
    float sn, cs;
    sincosf((float)w * invf, &sn, &cs);
    g_rotc[i*WW + w] = cs;
    g_rots[i*WW + w] = sn;
}

// ============================================================
// Kernel 1: 3x3 conv, 8->8 ch, all three projections at once.
// ============================================================
__global__ __launch_bounds__(256) void conv1_kernel(
    const float* __restrict__ x,
    const float* __restrict__ wq,
    const float* __restrict__ wk,
    const float* __restrict__ wv)
{
    int f = blockIdx.x, b = blockIdx.y;
    extern __shared__ float sm[];
    float* xs = sm;                      // [3][CC][WW+2]
    float* wt = sm + 3*CC*(WW+2);        // [3][MM][CC][9]
    int tid = threadIdx.x;

    for (int idx = tid; idx < 3*CC*(WW+2); idx += 256) {
        int r   = idx / (CC*(WW+2));
        int rem = idx % (CC*(WW+2));
        int c   = rem / (WW+2);
        int w   = rem % (WW+2) - 1;
        int fr  = f + r - 1;
        float v = 0.f;
        if (fr >= 0 && fr < FF && w >= 0 && w < WW)
            v = x[((b*CC + c)*FF + fr)*WW + w];
        xs[idx] = v;
    }
    for (int idx = tid; idx < MM*CC*9; idx += 256) {
        wt[idx]              = wq[idx];
        wt[idx +   MM*CC*9]  = wk[idx];
        wt[idx + 2*MM*CC*9]  = wv[idx];
    }
    __syncthreads();

    for (int o = tid; o < 3*MM*WW; o += 256) {
        int p = o / (MM*WW);
        int m = (o / WW) % MM;
        int w = o % WW;
        const float* wpt = wt + (p*MM + m)*CC*9;
        float acc = 0.f;
        #pragma unroll
        for (int c = 0; c < CC; c++) {
            #pragma unroll
            for (int r = 0; r < 3; r++) {
                const float* xr = xs + (r*CC + c)*(WW+2) + w;
                acc += xr[0]*wpt[c*9 + r*3 + 0];
                acc += xr[1]*wpt[c*9 + r*3 + 1];
                acc += xr[2]*wpt[c*9 + r*3 + 2];
            }
        }
        g_c1[p*BMFW + ((b*MM + m)*FF + f)*WW + w] = acc;
    }
}

// ============================================================
// Kernel 2: batched GEMM, 128x64 tiles, 8x4 microtile.
// ============================================================
__global__ __launch_bounds__(256) void gemm_lin_kernel(
    const float* __restrict__ Aq,
    const float* __restrict__ Ak,
    const float* __restrict__ Av)
{
    __shared__ float As[128*17];
    __shared__ float Bs[16*64];
    int z = blockIdx.z;
    int p = z >> 4;
    int n = z & 15;
    int m = n % MM;
    int g0 = blockIdx.y * 128, w0 = blockIdx.x * 64;
    const float* A = (p == 0) ? Aq : (p == 1) ? Ak : Av;
    const float* Ap = A + m*FF*FF;
    const float* Bp = g_c1  + (size_t)p*BMFW + (size_t)n*FF*WW;
    float*       Cp = g_lin + (size_t)p*BMFW + (size_t)n*FF*WW;
    int tx = threadIdx.x, ty = threadIdx.y;
    int tid = ty*16 + tx;

    float acc[8][4] = {};
    for (int f0 = 0; f0 < FF; f0 += 16) {
        #pragma unroll
        for (int u = 0; u < 2; u++) {
            int idx = tid + u*256;
            int r = idx >> 2;
            int c4 = (idx & 3) * 4;
            float4 a4 = *(const float4*)(Ap + (g0+r)*FF + f0 + c4);
            As[r*17 + c4+0] = a4.x; As[r*17 + c4+1] = a4.y;
            As[r*17 + c4+2] = a4.z; As[r*17 + c4+3] = a4.w;
        }
        {
            int fl = tid >> 4;
            int wl = (tid & 15) * 4;
            *(float4*)(Bs + fl*64 + wl) =
                *(const float4*)(Bp + (f0+fl)*WW + w0 + wl);
        }
        __syncthreads();
        #pragma unroll
        for (int k = 0; k < 16; k++) {
            float a[8];
            #pragma unroll
            for (int i = 0; i < 8; i++) a[i] = As[(ty*8+i)*17 + k];
            float4 b4 = *(const float4*)(Bs + k*64 + tx*4);
            float bf[4] = {b4.x, b4.y, b4.z, b4.w};
            #pragma unroll
            for (int i = 0; i < 8; i++)
                #pragma unroll
                for (int j = 0; j < 4; j++)
                    acc[i][j] += a[i]*bf[j];
        }
        __syncthreads();
    }
    #pragma unroll
    for (int i = 0; i < 8; i++) {
        float4 o4 = make_float4(acc[i][0], acc[i][1], acc[i][2], acc[i][3]);
        *(float4*)(Cp + (g0 + ty*8 + i)*WW + w0 + tx*4) = o4;
    }
}

// ============================================================
// Kernel 3: 1x3 conv across M + rotary, all 3 projections (z).
// ============================================================
__global__ __launch_bounds__(256) void conv2_rot_kernel(
    const float* __restrict__ wq2,
    const float* __restrict__ wk2,
    const float* __restrict__ wv2)
{
    int e = blockIdx.x, b = blockIdx.y, p = blockIdx.z;
    int f0 = 2*e;
    int apply_rot = (p < 2);
    const float* wc2 = (p == 0) ? wq2 : (p == 1) ? wk2 : wv2;
    const float* src = g_lin + (size_t)p*BMFW;
    float*       dst = g_qkv + (size_t)p*BMFW;

    __shared__ float hs[2*MM*(WW+2)];
    __shared__ float wt[MM*MM*3];
    __shared__ float rc[WW], rs[WW];
    int tid = threadIdx.x;

    for (int idx = tid; idx < 2*MM*(WW+2); idx += 256) {
        int rr  = idx / (MM*(WW+2));
        int rem = idx % (MM*(WW+2));
        int mm  = rem / (WW+2);
        int w   = rem % (WW+2) - 1;
        float v = 0.f;
        if (w >= 0 && w < WW)
            v = src[((b*MM + mm)*FF + f0 + rr)*WW + w];
        hs[idx] = v;
    }
    for (int idx = tid; idx < MM*MM*3; idx += 256) wt[idx] = wc2[idx];
    if (apply_rot) {
        int i = e % (HD/2);
        for (int w = tid; w < WW; w += 256) {
            rc[w] = g_rotc[i*WW + w];
            rs[w] = g_rots[i*WW + w];
        }
    }
    __syncthreads();

    for (int o = tid; o < MM*WW; o += 256) {
        int m = o / WW, w = o % WW;
        float c0 = 0.f, c1 = 0.f;
        #pragma unroll
        for (int mm = 0; mm < MM; mm++) {
            float k0 = wt[(m*MM+mm)*3+0];
            float k1 = wt[(m*MM+mm)*3+1];
            float k2 = wt[(m*MM+mm)*3+2];
            const float* h0 = hs + mm*(WW+2) + w;
            const float* h1 = hs + (MM+mm)*(WW+2) + w;
            c0 += h0[0]*k0 + h0[1]*k1 + h0[2]*k2;
            c1 += h1[0]*k0 + h1[1]*k1 + h1[2]*k2;
        }
        float o0 = c0, o1 = c1;
        if (apply_rot) {
            float cs = rc[w], sn = rs[w];
            o0 = c0*cs - c1*sn;
            o1 = c1*cs + c0*sn;
        }
        dst[((b*MM + m)*FF + f0    )*WW + w] = o0;
        dst[((b*MM + m)*FF + f0 + 1)*WW + w] = o1;
    }
}

// ============================================================
// Kernel 4: FUSED attention per (rowblock, tile). 256 threads.
// Per 128-col chunk: S GEMM (8x8 microtile) -> epilogue
// (prev add, Sout store, exp -> P in SMEM, rowsum) -> PV partial
// accumulation. P never touches gmem. Normalize at end.
// ============================================================
#define PPAD 132

__global__ __launch_bounds__(256) void attn_fused_kernel(
    const float* __restrict__ prev_qk,
    float* __restrict__ qk_out)
{
    int rb = blockIdx.x, t = blockIdx.y;
    int r0 = rb * 128;
    int h = t % HH, m = (t / HH) % MM, b = t / (HH*MM);

    extern __shared__ float smx[];
    float* Qt   = smx;                  // [32][PPAD]   16.9 KB
    float* Kt   = Qt  + 32*PPAD;        // [32][PPAD]   16.9 KB
    float* Pch  = Kt  + 32*PPAD;        // [128][PPAD]  67.6 KB
    float* Vs   = Pch + 128*PPAD;       // [512][32]    65.5 KB
    float* part = Vs  + 512*32;         // [16][128]     8.2 KB
    float* sinv = part + 16*128;        // [128]

    int tid = threadIdx.x;
    int tx = tid & 15, ty = tid >> 4;

    const float* Qb = g_qkv + 0*BMFW + ((b*MM+m)*FF + h*HD)*WW;
    const float* Kb = g_qkv + 1*BMFW + ((b*MM+m)*FF + h*HD)*WW;
    const float* Vb = g_qkv + 2*BMFW + ((b*MM+m)*FF + h*HD)*WW;
    const float* Pq   = prev_qk + (size_t)t*WW2;
    float*       Sout = qk_out  + (size_t)t*WW2;
    float*       At   = g_at + (size_t)(b*MM+m)*WW*FF + h*HD;

    // load Q^T subtile Qt[k][r] and all of V as Vs[j][d]
    #pragma unroll
    for (int u = 0; u < 4; u++) {
        int fid = tid + u*256;          // [0,1024)
        int d   = fid >> 5;
        int c4  = (fid & 31) * 4;
        float4 q4 = *(const float4*)(Qb + d*WW + r0 + c4);
        *(float4*)(Qt + d*PPAD + c4) = q4;
    }
    for (int idx = tid; idx < HD*WW; idx += 256) {
        int d = idx >> 9, w = idx & 511;
        Vs[w*32 + d] = Vb[d*WW + w];
    }

    float rsum[8];
    float pv[8][2];
    #pragma unroll
    for (int i = 0; i < 8; i++) {
        rsum[i] = 0.f; pv[i][0] = 0.f; pv[i][1] = 0.f;
    }

    const float scale = 0.0625f;

    for (int cc = 0; cc < 4; cc++) {
        int j0 = cc * 128;
        __syncthreads();   // Qt/Vs ready (it 0); Pch consumed by PV (it>0)
        #pragma unroll
        for (int u = 0; u < 4; u++) {
            int fid = tid + u*256;
            int d   = fid >> 5;
            int c4  = (fid & 31) * 4;
            float4 k4 = *(const float4*)(Kb + d*WW + j0 + c4);
            *(float4*)(Kt + d*PPAD + c4) = k4;
        }
        __syncthreads();

        // ---- S GEMM: 128x128, K=32, 8x8 microtile ----
        float acc[8][8];
        #pragma unroll
        for (int i = 0; i < 8; i++)
            #pragma unroll
            for (int j = 0; j < 8; j++) acc[i][j] = 0.f;

        #pragma unroll 4
        for (int k = 0; k < 32; k++) {
            float4 a0 = *(const float4*)(Qt + k*PPAD + ty*8);
            float4 a1 = *(const float4*)(Qt + k*PPAD + ty*8 + 4);
            float4 b0 = *(const float4*)(Kt + k*PPAD + tx*8);
            float4 b1 = *(const float4*)(Kt + k*PPAD + tx*8 + 4);
            float av[8] = {a0.x,a0.y,a0.z,a0.w,a1.x,a1.y,a1.z,a1.w};
            float bv[8] = {b0.x,b0.y,b0.z,b0.w,b1.x,b1.y,b1.z,b1.w};
            #pragma unroll
            for (int i = 0; i < 8; i++)
                #pragma unroll
                for (int j = 0; j < 8; j++)
                    acc[i][j] += av[i]*bv[j];
        }

        // ---- epilogue: prev add, Sout, exp -> Pch(smem), rowsum ----
        #pragma unroll
        for (int i = 0; i < 8; i++) {
            size_t rowoff = (size_t)(r0 + ty*8 + i)*WW + j0 + tx*8;
            float* pp = Pch + (ty*8 + i)*PPAD + tx*8;
            #pragma unroll
            for (int v = 0; v < 2; v++) {
                float4 pq4 = *(const float4*)(Pq + rowoff + v*4);
                float4 s4;
                s4.x = fmaf(acc[i][v*4+0], scale, pq4.x);
                s4.y = fmaf(acc[i][v*4+1], scale, pq4.y);
                s4.z = fmaf(acc[i][v*4+2], scale, pq4.z);
                s4.w = fmaf(acc[i][v*4+3], scale, pq4.w);
                *(float4*)(Sout + rowoff + v*4) = s4;
                float4 e4;
                e4.x = __expf(s4.x); e4.y = __expf(s4.y);
                e4.z = __expf(s4.z); e4.w = __expf(s4.w);
                *(float4*)(pp + v*4) = e4;
                rsum[i] += e4.x + e4.y + e4.z + e4.w;
            }
        }
        __syncthreads();   // Pch ready

        // ---- PV partial: rows ty*8.., d = tx*2..+1 ----
        const float* vb2 = Vs + j0*32 + tx*2;
        #pragma unroll 2
        for (int j4 = 0; j4 < 128; j4 += 4) {
            float4 p[8];
            #pragma unroll
            for (int i = 0; i < 8; i++)
                p[i] = *(const float4*)(Pch + (ty*8+i)*PPAD + j4);
            float2 v0 = *(const float2*)(vb2 + (j4+0)*32);
            float2 v1 = *(const float2*)(vb2 + (j4+1)*32);
            float2 v2 = *(const float2*)(vb2 + (j4+2)*32);
            float2 v3 = *(const float2*)(vb2 + (j4+3)*32);
            #pragma unroll
            for (int i = 0; i < 8; i++) {
                pv[i][0] += p[i].x*v0.x + p[i].y*v1.x + p[i].z*v2.x + p[i].w*v3.x;
                pv[i][1] += p[i].x*v0.y + p[i].y*v1.y + p[i].z*v2.y + p[i].w*v3.y;
            }
        }
    }

    // ---- rowsum block-reduce -> sinv ----
    #pragma unroll
    for (int i = 0; i < 8; i++) part[tx*128 + ty*8 + i] = rsum[i];
    __syncthreads();
    if (tid < 128) {
        float s = 0.f;
        #pragma unroll
        for (int u = 0; u < 16; u++) s += part[u*128 + tid];
        sinv[tid] = 1.0f / s;
    }
    __syncthreads();

    // ---- normalize + store A ----
    #pragma unroll
    for (int i = 0; i < 8; i++) {
        int r = r0 + ty*8 + i;
        float is = sinv[ty*8 + i];
        float2 o2 = make_float2(pv[i][0]*is, pv[i][1]*is);
        *(float2*)(At + (size_t)r*FF + tx*2) = o2;
    }
}

// ============================================================
// Kernel 5: out projection, 128x64 tiles, 8x4 microtile.
// ============================================================
__global__ __launch_bounds__(256) void gemm_out_kernel(
    const float* __restrict__ A,
    const float* __restrict__ Bt,
    float* __restrict__ Cx)
{
    __shared__ float As[128*17];
    __shared__ float Bs[64*17];
    int n = blockIdx.z;
    int m = n % MM;
    int g0 = blockIdx.y * 128, w0 = blockIdx.x * 64;
    const float* Ap = A  + m*FF*FF;
    const float* Bp = Bt + (size_t)n*WW*FF;
    int tx = threadIdx.x, ty = threadIdx.y;
    int tid = ty*16 + tx;

    float acc[8][4] = {};
    for (int f0 = 0; f0 < FF; f0 += 16) {
        #pragma unroll
        for (int u = 0; u < 2; u++) {
            int idx = tid + u*256;
            int r = idx >> 2;
            int c4 = (idx & 3) * 4;
            float4 a4 = *(const float4*)(Ap + (g0+r)*FF + f0 + c4);
            As[r*17 + c4+0] = a4.x; As[r*17 + c4+1] = a4.y;
            As[r*17 + c4+2] = a4.z; As[r*17 + c4+3] = a4.w;
        }
        {
            int wl = tid >> 2;
            int c4 = (tid & 3) * 4;
            float4 b4 = *(const float4*)(Bp + (size_t)(w0+wl)*FF + f0 + c4);
            Bs[wl*17 + c4+0] = b4.x; Bs[wl*17 + c4+1] = b4.y;
            Bs[wl*17 + c4+2] = b4.z; Bs[wl*17 + c4+3] = b4.w;
        }
        __syncthreads();
        #pragma unroll
        for (int k = 0; k < 16; k++) {
            float a[8], bf[4];
            #pragma unroll
            for (int i = 0; i < 8; i++) a[i]  = As[(ty*8+i)*17 + k];
            #pragma unroll
            for (int j = 0; j < 4; j++) bf[j] = Bs[(tx*4+j)*17 + k];
            #pragma unroll
            for (int i = 0; i < 8; i++)
                #pragma unroll
                for (int j = 0; j < 4; j++)
                    acc[i][j] += a[i]*bf[j];
        }
        __syncthreads();
    }
    #pragma unroll
    for (int i = 0; i < 8; i++) {
        float4 o4 = make_float4(acc[i][0], acc[i][1], acc[i][2], acc[i][3]);
        *(float4*)(Cx + ((size_t)n*FF + g0 + ty*8 + i)*WW + w0 + tx*4) = o4;
    }
}

// ============================================================
extern "C" void kernel_launch(void* const* d_in, const int* in_sizes, int n_in,
                              void* d_out, int out_size)
{
    const float* x       = (const float*)d_in[0];
    const float* prev_qk = (const float*)d_in[1];
    const float* ow      = (const float*)d_in[11];

    float* out_ptr = (float*)d_out;                // (B,M,F,W) first
    float* qk_ptr  = out_ptr + (size_t)BMFW;       // (B,M,H,W,W) second

    float* p_at;
    cudaGetSymbolAddress((void**)&p_at, g_at);

    // rotary table
    rot_table_kernel<<<16, WW>>>();

    // conv1
    int conv1_smem = (3*CC*(WW+2) + 3*MM*CC*9) * 4;
    cudaFuncSetAttribute(conv1_kernel,
        cudaFuncAttributeMaxDynamicSharedMemorySize, conv1_smem);
    conv1_kernel<<<dim3(FF, BB), 256, conv1_smem>>>(
        x, (const float*)d_in[2], (const float*)d_in[5], (const float*)d_in[8]);

    // lin GEMMs
    gemm_lin_kernel<<<dim3(WW/64, FF/128, 3*BB*MM), dim3(16,16)>>>(
        (const float*)d_in[3], (const float*)d_in[6], (const float*)d_in[9]);

    // conv2 (+rotary)
    conv2_rot_kernel<<<dim3(FF/2, BB, 3), 256>>>(
        (const float*)d_in[4], (const float*)d_in[7], (const float*)d_in[10]);

    // fused attention (S + softmax + PV; P stays in smem)
    int attn_smem = (32*PPAD + 32*PPAD + 128*PPAD + 512*32 + 16*128 + 128) * 4;
    cudaFuncSetAttribute(attn_fused_kernel,
        cudaFuncAttributeMaxDynamicSharedMemorySize, attn_smem);
    attn_fused_kernel<<<dim3(4, NT), 256, attn_smem>>>(prev_qk, qk_ptr);

    // output projection
    gemm_out_kernel<<<dim3(WW/64, FF/128, BB*MM), dim3(16,16)>>>(ow, p_at, out_ptr);
}

// round 13
// speedup vs baseline: 1.2087x; 1.0076x over previous
#include <cuda_runtime.h>
#include <math.h>

#define BB 2
#define CC 8
#define MM 8
#define HH 8
#define FF 256
#define WW 512
#define HD 32
#define BMFW (BB*MM*FF*WW)   // 2,097,152
#define NT  (BB*MM*HH)       // 128 attention tiles
#define WW2 (WW*WW)          // 262144

// ---- scratch (static device memory; no allocation) ----
__device__ float g_c1[3*BMFW];     // conv1 outputs for q,k,v
__device__ float g_lin[3*BMFW];    // lin outputs q,k,v
__device__ float g_qkv[3*BMFW];    // q,k,v post conv2(+rotary), layout [b][m][f][w]
__device__ float g_at[BMFW];       // attention out, layout [b][m][w][f]
__device__ float g_rotc[16*WW];
__device__ float g_rots[16*WW];

// ---- cp.async helpers ----
__device__ __forceinline__ void cp_async16(void* smem, const void* gmem) {
    unsigned s = (unsigned)__cvta_generic_to_shared(smem);
    asm volatile("cp.async.ca.shared.global [%0], [%1], 16;\n"
                 :: "r"(s), "l"(gmem) : "memory");
}
__device__ __forceinline__ void cp_async_commit() {
    asm volatile("cp.async.commit_group;\n" ::: "memory");
}
__device__ __forceinline__ void cp_async_wait_all() {
    asm volatile("cp.async.wait_group 0;\n" ::: "memory");
}

// ============================================================
// Kernel 0: rotary table
// ============================================================
__global__ void rot_table_kernel()
{
    int i = blockIdx.x, w = threadIdx.x;
    float invf = expf(-(float)i * (9.210340371976184f / 16.0f));
    float sn, cs;
    sincosf((float)w * invf, &sn, &cs);
    g_rotc[i*WW + w] = cs;
    g_rots[i*WW + w] = sn;
}

// ============================================================
// Kernel 1: 3x3 conv, 8->8 ch, all three projections at once.
// ============================================================
__global__ __launch_bounds__(256) void conv1_kernel(
    const float* __restrict__ x,
    const float* __restrict__ wq,
    const float* __restrict__ wk,
    const float* __restrict__ wv)
{
    int f = blockIdx.x, b = blockIdx.y;
    extern __shared__ float sm[];
    float* xs = sm;                      // [3][CC][WW+2]
    float* wt = sm + 3*CC*(WW+2);        // [3][MM][CC][9]
    int tid = threadIdx.x;

    for (int idx = tid; idx < 3*CC*(WW+2); idx += 256) {
        int r   = idx / (CC*(WW+2));
        int rem = idx % (CC*(WW+2));
        int c   = rem / (WW+2);
        int w   = rem % (WW+2) - 1;
        int fr  = f + r - 1;
        float v = 0.f;
        if (fr >= 0 && fr < FF && w >= 0 && w < WW)
            v = x[((b*CC + c)*FF + fr)*WW + w];
        xs[idx] = v;
    }
    for (int idx = tid; idx < MM*CC*9; idx += 256) {
        wt[idx]              = wq[idx];
        wt[idx +   MM*CC*9]  = wk[idx];
        wt[idx + 2*MM*CC*9]  = wv[idx];
    }
    __syncthreads();

    for (int o = tid; o < 3*MM*WW; o += 256) {
        int p = o / (MM*WW);
        int m = (o / WW) % MM;
        int w = o % WW;
        const float* wpt = wt + (p*MM + m)*CC*9;
        float acc = 0.f;
        #pragma unroll
        for (int c = 0; c < CC; c++) {
            #pragma unroll
            for (int r = 0; r < 3; r++) {
                const float* xr = xs + (r*CC + c)*(WW+2) + w;
                acc += xr[0]*wpt[c*9 + r*3 + 0];
                acc += xr[1]*wpt[c*9 + r*3 + 1];
                acc += xr[2]*wpt[c*9 + r*3 + 2];
            }
        }
        g_c1[p*BMFW + ((b*MM + m)*FF + f)*WW + w] = acc;
    }
}

// ============================================================
// Kernel 2: batched GEMM, 128x64 tiles, 8x4 microtile.
// ============================================================
__global__ __launch_bounds__(256) void gemm_lin_kernel(
    const float* __restrict__ Aq,
    const float* __restrict__ Ak,
    const float* __restrict__ Av)
{
    __shared__ float As[128*17];
    __shared__ float Bs[16*64];
    int z = blockIdx.z;
    int p = z >> 4;
    int n = z & 15;
    int m = n % MM;
    int g0 = blockIdx.y * 128, w0 = blockIdx.x * 64;
    const float* A = (p == 0) ? Aq : (p == 1) ? Ak : Av;
    const float* Ap = A + m*FF*FF;
    const float* Bp = g_c1  + (size_t)p*BMFW + (size_t)n*FF*WW;
    float*       Cp = g_lin + (size_t)p*BMFW + (size_t)n*FF*WW;
    int tx = threadIdx.x, ty = threadIdx.y;
    int tid = ty*16 + tx;

    float acc[8][4] = {};
    for (int f0 = 0; f0 < FF; f0 += 16) {
        #pragma unroll
        for (int u = 0; u < 2; u++) {
            int idx = tid + u*256;
            int r = idx >> 2;
            int c4 = (idx & 3) * 4;
            float4 a4 = *(const float4*)(Ap + (g0+r)*FF + f0 + c4);
            As[r*17 + c4+0] = a4.x; As[r*17 + c4+1] = a4.y;
            As[r*17 + c4+2] = a4.z; As[r*17 + c4+3] = a4.w;
        }
        {
            int fl = tid >> 4;
            int wl = (tid & 15) * 4;
            *(float4*)(Bs + fl*64 + wl) =
                *(const float4*)(Bp + (f0+fl)*WW + w0 + wl);
        }
        __syncthreads();
        #pragma unroll
        for (int k = 0; k < 16; k++) {
            float a[8];
            #pragma unroll
            for (int i = 0; i < 8; i++) a[i] = As[(ty*8+i)*17 + k];
            float4 b4 = *(const float4*)(Bs + k*64 + tx*4);
            float bf[4] = {b4.x, b4.y, b4.z, b4.w};
            #pragma unroll
            for (int i = 0; i < 8; i++)
                #pragma unroll
                for (int j = 0; j < 4; j++)
                    acc[i][j] += a[i]*bf[j];
        }
        __syncthreads();
    }
    #pragma unroll
    for (int i = 0; i < 8; i++) {
        float4 o4 = make_float4(acc[i][0], acc[i][1], acc[i][2], acc[i][3]);
        *(float4*)(Cp + (g0 + ty*8 + i)*WW + w0 + tx*4) = o4;
    }
}

// ============================================================
// Kernel 3: 1x3 conv across M + rotary, all 3 projections (z).
// 4 consecutive w per thread (window reuse), float4 stores.
// ============================================================
__global__ __launch_bounds__(256) void conv2_rot_kernel(
    const float* __restrict__ wq2,
    const float* __restrict__ wk2,
    const float* __restrict__ wv2)
{
    int e = blockIdx.x, b = blockIdx.y, p = blockIdx.z;
    int f0 = 2*e;
    int apply_rot = (p < 2);
    const float* wc2 = (p == 0) ? wq2 : (p == 1) ? wk2 : wv2;
    const float* src = g_lin + (size_t)p*BMFW;
    float*       dst = g_qkv + (size_t)p*BMFW;

    __shared__ float hs[2*MM*(WW+2)];
    __shared__ float wt[MM*MM*3];
    __shared__ float rc[WW], rs[WW];
    int tid = threadIdx.x;

    for (int idx = tid; idx < 2*MM*(WW+2); idx += 256) {
        int rr  = idx / (MM*(WW+2));
        int rem = idx % (MM*(WW+2));
        int mm  = rem / (WW+2);
        int w   = rem % (WW+2) - 1;
        float v = 0.f;
        if (w >= 0 && w < WW)
            v = src[((b*MM + mm)*FF + f0 + rr)*WW + w];
        hs[idx] = v;
    }
    for (int idx = tid; idx < MM*MM*3; idx += 256) wt[idx] = wc2[idx];
    if (apply_rot) {
        int i = e % (HD/2);
        for (int w = tid; w < WW; w += 256) {
            rc[w] = g_rotc[i*WW + w];
            rs[w] = g_rots[i*WW + w];
        }
    }
    __syncthreads();

    for (int o = tid; o < MM*(WW/4); o += 256) {
        int m  = o >> 7;            // WW/4 = 128
        int w4 = (o & 127) * 4;
        float c0[4] = {0.f,0.f,0.f,0.f};
        float c1[4] = {0.f,0.f,0.f,0.f};
        #pragma unroll
        for (int mm = 0; mm < MM; mm++) {
            float k0 = wt[(m*MM+mm)*3+0];
            float k1 = wt[(m*MM+mm)*3+1];
            float k2 = wt[(m*MM+mm)*3+2];
            const float* h0 = hs + mm*(WW+2) + w4;
            const float* h1 = hs + (MM+mm)*(WW+2) + w4;
            float a0=h0[0],a1=h0[1],a2=h0[2],a3=h0[3],a4=h0[4],a5=h0[5];
            c0[0] += a0*k0 + a1*k1 + a2*k2;
            c0[1] += a1*k0 + a2*k1 + a3*k2;
            c0[2] += a2*k0 + a3*k1 + a4*k2;
            c0[3] += a3*k0 + a4*k1 + a5*k2;
            float e0=h1[0],e1=h1[1],e2=h1[2],e3=h1[3],e4=h1[4],e5=h1[5];
            c1[0] += e0*k0 + e1*k1 + e2*k2;
            c1[1] += e1*k0 + e2*k1 + e3*k2;
            c1[2] += e2*k0 + e3*k1 + e4*k2;
            c1[3] += e3*k0 + e4*k1 + e5*k2;
        }
        float4 o0, o1;
        float* po0 = (float*)&o0;
        float* po1 = (float*)&o1;
        if (apply_rot) {
            #pragma unroll
            for (int u = 0; u < 4; u++) {
                float cs = rc[w4+u], sn = rs[w4+u];
                po0[u] = c0[u]*cs - c1[u]*sn;
                po1[u] = c1[u]*cs + c0[u]*sn;
            }
        } else {
            #pragma unroll
            for (int u = 0; u < 4; u++) { po0[u] = c0[u]; po1[u] = c1[u]; }
        }
        *(float4*)(dst + ((size_t)(b*MM + m)*FF + f0    )*WW + w4) = o0;
        *(float4*)(dst + ((size_t)(b*MM + m)*FF + f0 + 1)*WW + w4) = o1;
    }
}

// ============================================================
// Kernel 4: FUSED attention per (rowblock, tile). 256 threads.
// Per 128-col chunk:
//   prefetch prev chunk -> Pch via cp.async (overlaps S GEMM)
//   S GEMM (8x8 microtile) -> epilogue (prev from smem, Sout,
//   exp -> Pch, rowsum) -> PV partials (8 rows x 4 d x j-half).
// P never touches gmem. j-half reduce + normalize at end.
// ============================================================
#define PPAD 132

__global__ __launch_bounds__(256) void attn_fused_kernel(
    const float* __restrict__ prev_qk,
    float* __restrict__ qk_out)
{
    int rb = blockIdx.x, t = blockIdx.y;
    int r0 = rb * 128;
    int h = t % HH, m = (t / HH) % MM, b = t / (HH*MM);

    extern __shared__ float smx[];
    float* Qt   = smx;                  // [32][PPAD]   16.9 KB
    float* Kt   = Qt  + 32*PPAD;        // [32][PPAD]   16.9 KB
    float* Pch  = Kt  + 32*PPAD;        // [128][PPAD]  67.6 KB (also red buf)
    float* Vs   = Pch + 128*PPAD;       // [512][32]    65.5 KB
    float* part = Vs  + 512*32;         // [16][128]     8.2 KB
    float* sinv = part + 16*128;        // [128]

    int tid = threadIdx.x;
    int tx = tid & 15, ty = tid >> 4;
    int dg = tx & 7, jh = tx >> 3;      // PV mapping: 4 d per dg, j-half jh

    const float* Qb = g_qkv + 0*BMFW + ((b*MM+m)*FF + h*HD)*WW;
    const float* Kb = g_qkv + 1*BMFW + ((b*MM+m)*FF + h*HD)*WW;
    const float* Vb = g_qkv + 2*BMFW + ((b*MM+m)*FF + h*HD)*WW;
    const float* Pq   = prev_qk + (size_t)t*WW2;
    float*       Sout = qk_out  + (size_t)t*WW2;
    float*       At   = g_at + (size_t)(b*MM+m)*WW*FF + h*HD;

    // load Q^T subtile Qt[k][r] and all of V as Vs[j][d]
    #pragma unroll
    for (int u = 0; u < 4; u++) {
        int fid = tid + u*256;          // [0,1024)
        int d   = fid >> 5;
        int c4  = (fid & 31) * 4;
        float4 q4 = *(const float4*)(Qb + d*WW + r0 + c4);
        *(float4*)(Qt + d*PPAD + c4) = q4;
    }
    for (int idx = tid; idx < HD*WW; idx += 256) {
        int d = idx >> 9, w = idx & 511;
        Vs[w*32 + d] = Vb[d*WW + w];
    }

    float rsum[8];
    float pv[8][4];
    #pragma unroll
    for (int i = 0; i < 8; i++) {
        rsum[i] = 0.f;
        #pragma unroll
        for (int d = 0; d < 4; d++) pv[i][d] = 0.f;
    }

    const float scale = 0.0625f;

    for (int cc = 0; cc < 4; cc++) {
        int j0 = cc * 128;
        __syncthreads();   // Qt/Vs ready (cc=0); all PV(cc-1) done

        // ---- prefetch prev chunk into own Pch slots (async) ----
        #pragma unroll
        for (int i = 0; i < 8; i++) {
            size_t rowoff = (size_t)(r0 + ty*8 + i)*WW + j0 + tx*8;
            float* pp = Pch + (ty*8 + i)*PPAD + tx*8;
            cp_async16(pp,     Pq + rowoff);
            cp_async16(pp + 4, Pq + rowoff + 4);
        }
        cp_async_commit();

        // ---- Kt chunk load ----
        #pragma unroll
        for (int u = 0; u < 4; u++) {
            int fid = tid + u*256;
            int d   = fid >> 5;
            int c4  = (fid & 31) * 4;
            float4 k4 = *(const float4*)(Kb + d*WW + j0 + c4);
            *(float4*)(Kt + d*PPAD + c4) = k4;
        }
        __syncthreads();

        // ---- S GEMM: 128x128, K=32, 8x8 microtile ----
        float acc[8][8];
        #pragma unroll
        for (int i = 0; i < 8; i++)
            #pragma unroll
            for (int j = 0; j < 8; j++) acc[i][j] = 0.f;

        #pragma unroll 4
        for (int k = 0; k < 32; k++) {
            float4 a0 = *(const float4*)(Qt + k*PPAD + ty*8);
            float4 a1 = *(const float4*)(Qt + k*PPAD + ty*8 + 4);
            float4 b0 = *(const float4*)(Kt + k*PPAD + tx*8);
            float4 b1 = *(const float4*)(Kt + k*PPAD + tx*8 + 4);
            float av[8] = {a0.x,a0.y,a0.z,a0.w,a1.x,a1.y,a1.z,a1.w};
            float bv[8] = {b0.x,b0.y,b0.z,b0.w,b1.x,b1.y,b1.z,b1.w};
            #pragma unroll
            for (int i = 0; i < 8; i++)
                #pragma unroll
                for (int j = 0; j < 8; j++)
                    acc[i][j] += av[i]*bv[j];
        }

        cp_async_wait_all();   // own prev slots resident in Pch

        // ---- epilogue: prev(smem) add, Sout, exp -> Pch, rowsum ----
        #pragma unroll
        for (int i = 0; i < 8; i++) {
            size_t rowoff = (size_t)(r0 + ty*8 + i)*WW + j0 + tx*8;
            float* pp = Pch + (ty*8 + i)*PPAD + tx*8;
            #pragma unroll
            for (int v = 0; v < 2; v++) {
                float4 pq4 = *(const float4*)(pp + v*4);
                float4 s4;
                s4.x = fmaf(acc[i][v*4+0], scale, pq4.x);
                s4.y = fmaf(acc[i][v*4+1], scale, pq4.y);
                s4.z = fmaf(acc[i][v*4+2], scale, pq4.z);
                s4.w = fmaf(acc[i][v*4+3], scale, pq4.w);
                *(float4*)(Sout + rowoff + v*4) = s4;
                float4 e4;
                e4.x = __expf(s4.x); e4.y = __expf(s4.y);
                e4.z = __expf(s4.z); e4.w = __expf(s4.w);
                *(float4*)(pp + v*4) = e4;
                rsum[i] += e4.x + e4.y + e4.z + e4.w;
            }
        }
        __syncthreads();   // Pch P ready

        // ---- PV partial: rows ty*8.., d = dg*4.., j in [jh*64, +64) ----
        {
            const float* vb = Vs + (j0 + jh*64)*32 + dg*4;
            const float* pb = Pch + jh*64;
            #pragma unroll 2
            for (int jj = 0; jj < 64; jj += 4) {
                float4 p[8];
                #pragma unroll
                for (int i = 0; i < 8; i++)
                    p[i] = *(const float4*)(pb + (ty*8+i)*PPAD + jj);
                float4 v0 = *(const float4*)(vb + (jj+0)*32);
                float4 v1 = *(const float4*)(vb + (jj+1)*32);
                float4 v2 = *(const float4*)(vb + (jj+2)*32);
                float4 v3 = *(const float4*)(vb + (jj+3)*32);
                #pragma unroll
                for (int i = 0; i < 8; i++) {
                    pv[i][0] += p[i].x*v0.x + p[i].y*v1.x + p[i].z*v2.x + p[i].w*v3.x;
                    pv[i][1] += p[i].x*v0.y + p[i].y*v1.y + p[i].z*v2.y + p[i].w*v3.y;
                    pv[i][2] += p[i].x*v0.z + p[i].y*v1.z + p[i].z*v2.z + p[i].w*v3.z;
                    pv[i][3] += p[i].x*v0.w + p[i].y*v1.w + p[i].z*v2.w + p[i].w*v3.w;
                }
            }
        }
    }

    __syncthreads();   // all PV done; Pch free for reduction reuse

    // ---- jh=1 partials -> Pch[r][d] ; rowsums -> part ----
    if (jh == 1) {
        #pragma unroll
        for (int i = 0; i < 8; i++) {
            float4 o4 = make_float4(pv[i][0], pv[i][1], pv[i][2], pv[i][3]);
            *(float4*)(Pch + (ty*8+i)*32 + dg*4) = o4;
        }
    }
    #pragma unroll
    for (int i = 0; i < 8; i++) part[tx*128 + ty*8 + i] = rsum[i];
    __syncthreads();

    if (tid < 128) {
        float s = 0.f;
        #pragma unroll
        for (int u = 0; u < 16; u++) s += part[u*128 + tid];
        sinv[tid] = 1.0f / s;
    }
    __syncthreads();

    // ---- jh=0: combine halves, normalize, store A ----
    if (jh == 0) {
        #pragma unroll
        for (int i = 0; i < 8; i++) {
            int rl = ty*8 + i;
            float is = sinv[rl];
            float4 r4 = *(const float4*)(Pch + rl*32 + dg*4);
            float4 o4;
            o4.x = (pv[i][0] + r4.x) * is;
            o4.y = (pv[i][1] + r4.y) * is;
            o4.z = (pv[i][2] + r4.z) * is;
            o4.w = (pv[i][3] + r4.w) * is;
            *(float4*)(At + (size_t)(r0 + rl)*FF + dg*4) = o4;
        }
    }
}

// ============================================================
// Kernel 5: out projection, 128x64 tiles, 8x4 microtile.
// ============================================================
__global__ __launch_bounds__(256) void gemm_out_kernel(
    const float* __restrict__ A,
    const float* __restrict__ Bt,
    float* __restrict__ Cx)
{
    __shared__ float As[128*17];
    __shared__ float Bs[64*17];
    int n = blockIdx.z;
    int m = n % MM;
    int g0 = blockIdx.y * 128, w0 = blockIdx.x * 64;
    const float* Ap = A  + m*FF*FF;
    const float* Bp = Bt + (size_t)n*WW*FF;
    int tx = threadIdx.x, ty = threadIdx.y;
    int tid = ty*16 + tx;

    float acc[8][4] = {};
    for (int f0 = 0; f0 < FF; f0 += 16) {
        #pragma unroll
        for (int u = 0; u < 2; u++) {
            int idx = tid + u*256;
            int r = idx >> 2;
            int c4 = (idx & 3) * 4;
            float4 a4 = *(const float4*)(Ap + (g0+r)*FF + f0 + c4);
            As[r*17 + c4+0] = a4.x; As[r*17 + c4+1] = a4.y;
            As[r*17 + c4+2] = a4.z; As[r*17 + c4+3] = a4.w;
        }
        {
            int wl = tid >> 2;
            int c4 = (tid & 3) * 4;
            float4 b4 = *(const float4*)(Bp + (size_t)(w0+wl)*FF + f0 + c4);
            Bs[wl*17 + c4+0] = b4.x; Bs[wl*17 + c4+1] = b4.y;
            Bs[wl*17 + c4+2] = b4.z; Bs[wl*17 + c4+3] = b4.w;
        }
        __syncthreads();
        #pragma unroll
        for (int k = 0; k < 16; k++) {
            float a[8], bf[4];
            #pragma unroll
            for (int i = 0; i < 8; i++) a[i]  = As[(ty*8+i)*17 + k];
            #pragma unroll
            for (int j = 0; j < 4; j++) bf[j] = Bs[(tx*4+j)*17 + k];
            #pragma unroll
            for (int i = 0; i < 8; i++)
                #pragma unroll
                for (int j = 0; j < 4; j++)
                    acc[i][j] += a[i]*bf[j];
        }
        __syncthreads();
    }
    #pragma unroll
    for (int i = 0; i < 8; i++) {
        float4 o4 = make_float4(acc[i][0], acc[i][1], acc[i][2], acc[i][3]);
        *(float4*)(Cx + ((size_t)n*FF + g0 + ty*8 + i)*WW + w0 + tx*4) = o4;
    }
}

// ============================================================
extern "C" void kernel_launch(void* const* d_in, const int* in_sizes, int n_in,
                              void* d_out, int out_size)
{
    const float* x       = (const float*)d_in[0];
    const float* prev_qk = (const float*)d_in[1];
    const float* ow      = (const float*)d_in[11];

    float* out_ptr = (float*)d_out;                // (B,M,F,W) first
    float* qk_ptr  = out_ptr + (size_t)BMFW;       // (B,M,H,W,W) second

    float* p_at;
    cudaGetSymbolAddress((void**)&p_at, g_at);

    // rotary table
    rot_table_kernel<<<16, WW>>>();

    // conv1
    int conv1_smem = (3*CC*(WW+2) + 3*MM*CC*9) * 4;
    cudaFuncSetAttribute(conv1_kernel,
        cudaFuncAttributeMaxDynamicSharedMemorySize, conv1_smem);
    conv1_kernel<<<dim3(FF, BB), 256, conv1_smem>>>(
        x, (const float*)d_in[2], (const float*)d_in[5], (const float*)d_in[8]);

    // lin GEMMs
    gemm_lin_kernel<<<dim3(WW/64, FF/128, 3*BB*MM), dim3(16,16)>>>(
        (const float*)d_in[3], (const float*)d_in[6], (const float*)d_in[9]);

    // conv2 (+rotary)
    conv2_rot_kernel<<<dim3(FF/2, BB, 3), 256>>>(
        (const float*)d_in[4], (const float*)d_in[7], (const float*)d_in[10]);

    // fused attention (S + softmax + PV; P stays in smem)
    int attn_smem = (32*PPAD + 32*PPAD + 128*PPAD + 512*32 + 16*128 + 128) * 4;
    cudaFuncSetAttribute(attn_fused_kernel,
        cudaFuncAttributeMaxDynamicSharedMemorySize, attn_smem);
    attn_fused_kernel<<<dim3(4, NT), 256, attn_smem>>>(prev_qk, qk_ptr);

    // output projection
    gemm_out_kernel<<<dim3(WW/64, FF/128, BB*MM), dim3(16,16)>>>(ow, p_at, out_ptr);
}